// round 7
// baseline (speedup 1.0000x reference)
#include <cuda_runtime.h>
#include <cuda_bf16.h>

#define KDIM 8
static const int MAXN  = 100000;
static const int MAXNK = MAXN * KDIM;

// Scratch (device globals — no cudaMalloc allowed).
__device__ float4 g_accQ4[MAXNK];   // seeded es*q, then += ee * (rel x q_src)
__device__ float2 g_accDL2[MAXNK];  // seeded {es, es*l}, then += {ee, ee*l}
__device__ float4 g_qp[MAXNK];      // packed: max(l,1e-8) * q   (norm encodes l)

// ---------------------------------------------------------------------------
// Prepass: build packed node table AND seed accumulators with the self term.
// Replaces the memsets and removes node-table reads from the finalize.
// ---------------------------------------------------------------------------
__global__ void __launch_bounds__(256)
spt_prep_kernel(const float* __restrict__ node_levels,
                const float4* __restrict__ node_q,
                int NK)
{
    int i = blockIdx.x * blockDim.x + threadIdx.x;
    if (i >= NK) return;
    float  l = node_levels[i];
    float4 q = node_q[i];
    float lc = fmaxf(l, 1e-8f);          // keep direction recoverable at l==0
    g_qp[i] = make_float4(lc * q.x, lc * q.y, lc * q.z, lc * q.w);
    float es = __expf(8.0f * l);         // self term (w = 1); shift cancels
    g_accQ4[i]  = make_float4(es * q.x, es * q.y, es * q.z, es * q.w);
    g_accDL2[i] = make_float2(es, es * l);
}

// ---------------------------------------------------------------------------
// Edge scatter. One thread per (edge, k); 8 lanes share one edge.
// Single 128B gather per edge (qp row); l recovered as ||qp||.
// DL pairs via shfl -> even lanes issue one v4 RED for two k's, issued
// before the Hamilton product to overlap the LSU queue with FMAs.
// ---------------------------------------------------------------------------
__global__ void __launch_bounds__(256)
spt_edge_kernel(const float4* __restrict__ edge_rel_q,
                const float*  __restrict__ edge_w,
                const int*    __restrict__ edge_src,
                const int*    __restrict__ edge_dst,
                long long EK)
{
    long long t = (long long)blockIdx.x * blockDim.x + threadIdx.x;
    bool active = (t < EK);
    long long tc = active ? t : 0;        // clamp for safe loads
    int e = (int)(tc >> 3);
    int k = (int)(tc & 7);

    int   s  = __ldg(edge_src + e);
    int   d  = __ldg(edge_dst + e);
    float w  = __ldg(edge_w + e);
    float4 rq = __ldg(edge_rel_q + e);

    int si = s * KDIM + k;
    float4 qp = __ldg(g_qp + si);         // = l * q_src, 128B line per edge

    float nq  = qp.x*qp.x + qp.y*qp.y + qp.z*qp.z + qp.w*qp.w;  // = l^2
    float invl = rsqrtf(nq);
    float l    = nq * invl;               // = sqrt(nq)

    float ee  = __expf(8.0f * w * l);     // exp_e (softmax shift cancels)
    float eel = ee * l;

    // Pair up DL values: even lane k takes lane k+1's {ee, eel}.
    float nee  = __shfl_down_sync(0xffffffffu, ee, 1);
    float neel = __shfl_down_sync(0xffffffffu, eel, 1);

    int di = d * KDIM + k;

    if (active && ((k & 1) == 0)) {
        float4* adl = (float4*)(g_accDL2 + di);  // 16B aligned (di even)
        asm volatile("red.global.add.v4.f32 [%0], {%1, %2, %3, %4};"
                     :: "l"(adl), "f"(ee), "f"(eel), "f"(nee), "f"(neel)
                     : "memory");
    }

    // Hamilton product rel_q (x) qp ; storage order (w,x,y,z).
    // qp = l*q_src, so scale payload by ee/l = ee*invl.
    float w1 = rq.x, x1 = rq.y, y1 = rq.z, z1 = rq.w;
    float w2 = qp.x, x2 = qp.y, y2 = qp.z, z2 = qp.w;
    float ow = w1*w2 - x1*x2 - y1*y2 - z1*z2;
    float ox = w1*x2 + x1*w2 + y1*z2 - z1*y2;
    float oy = w1*y2 - x1*z2 + y1*w2 + z1*x2;
    float oz = w1*z2 + x1*y2 - y1*x2 + z1*w2;

    float sc = ee * invl;

    if (active) {
        float4* aq = g_accQ4 + di;
        asm volatile("red.global.add.v4.f32 [%0], {%1, %2, %3, %4};"
                     :: "l"(aq), "f"(sc*ow), "f"(sc*ox), "f"(sc*oy), "f"(sc*oz)
                     : "memory");
    }
}

// ---------------------------------------------------------------------------
// Finalize (accumulators already include self term): divide + normalize.
// ---------------------------------------------------------------------------
__global__ void __launch_bounds__(256)
spt_final_kernel(float4* __restrict__ out_q,
                 float*  __restrict__ out_l,
                 int NK)
{
    int i = blockIdx.x * blockDim.x + threadIdx.x;
    if (i >= NK) return;

    float2 dl  = g_accDL2[i];
    float4 a   = g_accQ4[i];
    float  inv = 1.0f / dl.x;

    float qw = a.x * inv, qx = a.y * inv, qy = a.z * inv, qz = a.w * inv;
    float nrm = sqrtf(qw*qw + qx*qx + qy*qy + qz*qz);
    float r   = 1.0f / fmaxf(nrm, 1e-12f);
    out_q[i] = make_float4(qw * r, qx * r, qy * r, qz * r);
    out_l[i] = dl.y * inv;
}

// ---------------------------------------------------------------------------
// Launch. Inputs: 0 node_levels [N,K], 1 node_q [N,K,4], 2 edge_rel_q [E,4],
//                 3 edge_w [E], 4 edge_src [E], 5 edge_dst [E].
// Output: q [N,K,4] flattened, then out_levels [N,K].
// ---------------------------------------------------------------------------
extern "C" void kernel_launch(void* const* d_in, const int* in_sizes, int n_in,
                              void* d_out, int out_size)
{
    const float*  node_levels = (const float*) d_in[0];
    const float4* node_q      = (const float4*)d_in[1];
    const float4* edge_rel_q  = (const float4*)d_in[2];
    const float*  edge_w      = (const float*) d_in[3];
    const int*    edge_src    = (const int*)   d_in[4];
    const int*    edge_dst    = (const int*)   d_in[5];

    int NK = in_sizes[0];                 // N*K
    int E  = in_sizes[3];
    long long EK = (long long)E * KDIM;

    float4* out_q = (float4*)d_out;
    float*  out_l = (float*)d_out + (long long)NK * 4;

    const int TPB = 256;
    int grid_nk = (NK + TPB - 1) / TPB;
    int grid_ek = (int)((EK + TPB - 1) / TPB);

    spt_prep_kernel <<<grid_nk, TPB>>>(node_levels, node_q, NK);
    spt_edge_kernel <<<grid_ek, TPB>>>(edge_rel_q, edge_w, edge_src,
                                       edge_dst, EK);
    spt_final_kernel<<<grid_nk, TPB>>>(out_q, out_l, NK);
}

// round 8
// speedup vs baseline: 1.0098x; 1.0098x over previous
#include <cuda_runtime.h>
#include <cuda_bf16.h>

#define KDIM 8
static const int MAXN  = 100000;
static const int MAXNK = MAXN * KDIM;

// Scratch (device globals — no cudaMalloc allowed).
__device__ float4 g_accQ4[MAXNK];   // seeded es*q, then += ee * (rel x q_src)
__device__ float2 g_accDL2[MAXNK];  // seeded {es, es*l}, then += {ee, ee*l}
__device__ float4 g_qp[MAXNK];      // packed: max(l,1e-8) * q  (norm encodes l)

// ---------------------------------------------------------------------------
// Prepass: build packed node table AND seed accumulators with the self term.
// ---------------------------------------------------------------------------
__global__ void __launch_bounds__(256)
spt_prep_kernel(const float* __restrict__ node_levels,
                const float4* __restrict__ node_q,
                int NK)
{
    int i = blockIdx.x * blockDim.x + threadIdx.x;
    if (i >= NK) return;
    float  l = node_levels[i];
    float4 q = node_q[i];
    float lc = fmaxf(l, 1e-8f);          // keep direction recoverable at l==0
    g_qp[i] = make_float4(lc * q.x, lc * q.y, lc * q.z, lc * q.w);
    float es = __expf(8.0f * l);         // self term (w = 1); shift cancels
    g_accQ4[i]  = make_float4(es * q.x, es * q.y, es * q.z, es * q.w);
    g_accDL2[i] = make_float2(es, es * l);
}

// ---------------------------------------------------------------------------
// Edge scatter, 2 (edge,k) elements per thread: t and t + halfEK.
// halfEK is a multiple of 8 -> lane k identical for both elements, so the
// shfl DL-pairing (even lane covers k and k+1) works for both at once.
// All loads issued up front (MLP x2); DL REDs issued before Hamilton FMAs.
// ---------------------------------------------------------------------------
__global__ void __launch_bounds__(256)
spt_edge_kernel(const float4* __restrict__ edge_rel_q,
                const float*  __restrict__ edge_w,
                const int*    __restrict__ edge_src,
                const int*    __restrict__ edge_dst,
                long long halfEK)
{
    long long t = (long long)blockIdx.x * blockDim.x + threadIdx.x;
    bool active = (t < halfEK);
    long long tc = active ? t : 0;        // clamp for safe loads
    long long u0 = tc;
    long long u1 = tc + halfEK;
    int e0 = (int)(u0 >> 3);
    int e1 = (int)(u1 >> 3);
    int k  = (int)(u0 & 7);               // same k for u1 (halfEK % 8 == 0)

    // ---- issue all loads up front ----
    int   s0 = __ldg(edge_src + e0);
    int   s1 = __ldg(edge_src + e1);
    int   d0 = __ldg(edge_dst + e0);
    int   d1 = __ldg(edge_dst + e1);
    float w0 = __ldg(edge_w + e0);
    float w1 = __ldg(edge_w + e1);
    float4 rq0 = __ldg(edge_rel_q + e0);
    float4 rq1 = __ldg(edge_rel_q + e1);
    float4 qp0 = __ldg(g_qp + s0 * KDIM + k);   // 128B line per edge
    float4 qp1 = __ldg(g_qp + s1 * KDIM + k);

    // ---- element 0 scalar chain ----
    float nq0   = qp0.x*qp0.x + qp0.y*qp0.y + qp0.z*qp0.z + qp0.w*qp0.w;
    float invl0 = rsqrtf(nq0);
    float l0    = nq0 * invl0;
    float ee0   = __expf(8.0f * w0 * l0);
    float eel0  = ee0 * l0;

    // ---- element 1 scalar chain ----
    float nq1   = qp1.x*qp1.x + qp1.y*qp1.y + qp1.z*qp1.z + qp1.w*qp1.w;
    float invl1 = rsqrtf(nq1);
    float l1    = nq1 * invl1;
    float ee1   = __expf(8.0f * w1 * l1);
    float eel1  = ee1 * l1;

    // ---- DL pairing via shfl (even lane k covers k and k+1) ----
    float nee0  = __shfl_down_sync(0xffffffffu, ee0,  1);
    float neel0 = __shfl_down_sync(0xffffffffu, eel0, 1);
    float nee1  = __shfl_down_sync(0xffffffffu, ee1,  1);
    float neel1 = __shfl_down_sync(0xffffffffu, eel1, 1);

    int di0 = d0 * KDIM + k;
    int di1 = d1 * KDIM + k;

    if (active && ((k & 1) == 0)) {
        float4* adl0 = (float4*)(g_accDL2 + di0);   // 16B aligned (di even)
        float4* adl1 = (float4*)(g_accDL2 + di1);
        asm volatile("red.global.add.v4.f32 [%0], {%1, %2, %3, %4};"
                     :: "l"(adl0), "f"(ee0), "f"(eel0), "f"(nee0), "f"(neel0)
                     : "memory");
        asm volatile("red.global.add.v4.f32 [%0], {%1, %2, %3, %4};"
                     :: "l"(adl1), "f"(ee1), "f"(eel1), "f"(nee1), "f"(neel1)
                     : "memory");
    }

    // ---- Hamilton products (rel_q x qp; qp = l*q so scale by ee/l) ----
    float sc0 = ee0 * invl0;
    float sc1 = ee1 * invl1;

    float aw0, ax0, ay0, az0;
    {
        float w1q = rq0.x, x1q = rq0.y, y1q = rq0.z, z1q = rq0.w;
        float w2q = qp0.x, x2q = qp0.y, y2q = qp0.z, z2q = qp0.w;
        aw0 = sc0 * (w1q*w2q - x1q*x2q - y1q*y2q - z1q*z2q);
        ax0 = sc0 * (w1q*x2q + x1q*w2q + y1q*z2q - z1q*y2q);
        ay0 = sc0 * (w1q*y2q - x1q*z2q + y1q*w2q + z1q*x2q);
        az0 = sc0 * (w1q*z2q + x1q*y2q - y1q*x2q + z1q*w2q);
    }
    float aw1, ax1, ay1, az1;
    {
        float w1q = rq1.x, x1q = rq1.y, y1q = rq1.z, z1q = rq1.w;
        float w2q = qp1.x, x2q = qp1.y, y2q = qp1.z, z2q = qp1.w;
        aw1 = sc1 * (w1q*w2q - x1q*x2q - y1q*y2q - z1q*z2q);
        ax1 = sc1 * (w1q*x2q + x1q*w2q + y1q*z2q - z1q*y2q);
        ay1 = sc1 * (w1q*y2q - x1q*z2q + y1q*w2q + z1q*x2q);
        az1 = sc1 * (w1q*z2q + x1q*y2q - y1q*x2q + z1q*w2q);
    }

    if (active) {
        float4* aq0 = g_accQ4 + di0;
        float4* aq1 = g_accQ4 + di1;
        asm volatile("red.global.add.v4.f32 [%0], {%1, %2, %3, %4};"
                     :: "l"(aq0), "f"(aw0), "f"(ax0), "f"(ay0), "f"(az0)
                     : "memory");
        asm volatile("red.global.add.v4.f32 [%0], {%1, %2, %3, %4};"
                     :: "l"(aq1), "f"(aw1), "f"(ax1), "f"(ay1), "f"(az1)
                     : "memory");
    }
}

// ---------------------------------------------------------------------------
// Finalize (accumulators already include self term): divide + normalize.
// ---------------------------------------------------------------------------
__global__ void __launch_bounds__(256)
spt_final_kernel(float4* __restrict__ out_q,
                 float*  __restrict__ out_l,
                 int NK)
{
    int i = blockIdx.x * blockDim.x + threadIdx.x;
    if (i >= NK) return;

    float2 dl  = g_accDL2[i];
    float4 a   = g_accQ4[i];
    float  inv = 1.0f / dl.x;

    float qw = a.x * inv, qx = a.y * inv, qy = a.z * inv, qz = a.w * inv;
    float nrm = sqrtf(qw*qw + qx*qx + qy*qy + qz*qz);
    float r   = 1.0f / fmaxf(nrm, 1e-12f);
    out_q[i] = make_float4(qw * r, qx * r, qy * r, qz * r);
    out_l[i] = dl.y * inv;
}

// ---------------------------------------------------------------------------
// Launch. Inputs: 0 node_levels [N,K], 1 node_q [N,K,4], 2 edge_rel_q [E,4],
//                 3 edge_w [E], 4 edge_src [E], 5 edge_dst [E].
// Output: q [N,K,4] flattened, then out_levels [N,K].
// ---------------------------------------------------------------------------
extern "C" void kernel_launch(void* const* d_in, const int* in_sizes, int n_in,
                              void* d_out, int out_size)
{
    const float*  node_levels = (const float*) d_in[0];
    const float4* node_q      = (const float4*)d_in[1];
    const float4* edge_rel_q  = (const float4*)d_in[2];
    const float*  edge_w      = (const float*) d_in[3];
    const int*    edge_src    = (const int*)   d_in[4];
    const int*    edge_dst    = (const int*)   d_in[5];

    int NK = in_sizes[0];                 // N*K
    int E  = in_sizes[3];
    long long EK = (long long)E * KDIM;
    long long halfEK = EK / 2;            // E even -> halfEK % 8 == 0

    float4* out_q = (float4*)d_out;
    float*  out_l = (float*)d_out + (long long)NK * 4;

    const int TPB = 256;
    int grid_nk = (NK + TPB - 1) / TPB;
    int grid_e2 = (int)((halfEK + TPB - 1) / TPB);

    spt_prep_kernel <<<grid_nk, TPB>>>(node_levels, node_q, NK);
    spt_edge_kernel <<<grid_e2, TPB>>>(edge_rel_q, edge_w, edge_src,
                                       edge_dst, halfEK);
    spt_final_kernel<<<grid_nk, TPB>>>(out_q, out_l, NK);
}